// round 13
// baseline (speedup 1.0000x reference)
#include <cuda_runtime.h>
#include <cuda_fp16.h>
#include <cstdint>

// Problem constants
#define TT 16384   // B*S tokens
#define HH 1024    // hidden
#define II 4096    // intermediate
#define EE 8       // experts

// ---------------- scratch (device globals; no runtime allocation) ----------
__device__ int      d_counts[EE];
__device__ int      d_tok[EE * TT];
__device__ uint32_t d_slotEP[2 * TT];             // (expert<<20)|pos per token slot
__device__ float    d_wtok[2 * TT];               // per-token top-2 weights
__device__ __half   d_hmid[(size_t)2 * TT * II];  // fp16 intermediate (268 MB)
__device__ float    d_osc[(size_t)2 * TT * HH];   // fp32 expert outputs (134 MB)
__device__ __half   d_xh[(size_t)TT * HH];        // fp16 x (written by router)
__device__ __half   d_w1h[(size_t)EE * II * HH];  // fp16 W1
__device__ __half   d_w2h[(size_t)EE * HH * II];  // fp16 W2

// ---------------- helpers ----------------
__device__ __forceinline__ float silu_f(float v) { return v / (1.0f + __expf(-v)); }
__device__ __forceinline__ uint32_t smem_u32(const void* p) {
    uint32_t a;
    asm("{ .reg .u64 t; cvta.to.shared.u64 t, %1; cvt.u32.u64 %0, t; }" : "=r"(a) : "l"(p));
    return a;
}
__device__ __forceinline__ int expert_offset(int e) {
    int off = 0;
#pragma unroll
    for (int q = 0; q < EE; q++) off += (q < e) ? d_counts[q] : 0;
    return off;
}

// fp16-accumulate MMA, accumulating variant
#define MMA_F16H(Dh, A, B_)                                                      \
    asm volatile(                                                                \
        "mma.sync.aligned.m16n8k16.row.col.f16.f16.f16.f16 "                     \
        "{%0,%1}, {%2,%3,%4,%5}, {%6,%7}, {%0,%1};\n"                            \
        : "+r"((Dh)[0]), "+r"((Dh)[1])                                           \
        : "r"((A)[0]), "r"((A)[1]), "r"((A)[2]), "r"((A)[3]),                    \
          "r"((B_)[0]), "r"((B_)[1]))

// fp16-accumulate MMA, zero-C variant (group start; avoids explicit zeroing)
#define MMA_F16Z(Dh, A, B_)                                                      \
    asm volatile(                                                                \
        "mma.sync.aligned.m16n8k16.row.col.f16.f16.f16.f16 "                     \
        "{%0,%1}, {%2,%3,%4,%5}, {%6,%7}, {%8,%9};\n"                            \
        : "=r"((Dh)[0]), "=r"((Dh)[1])                                           \
        : "r"((A)[0]), "r"((A)[1]), "r"((A)[2]), "r"((A)[3]),                    \
          "r"((B_)[0]), "r"((B_)[1]), "r"(0u), "r"(0u))

#define LDSM_X4(r0, r1, r2, r3, addr)                                            \
    asm volatile("ldmatrix.sync.aligned.m8n8.x4.shared.b16 {%0,%1,%2,%3}, [%4];" \
        : "=r"(r0), "=r"(r1), "=r"(r2), "=r"(r3) : "r"(addr))

#define CP_ASYNC16(saddr, gptr) \
    asm volatile("cp.async.cg.shared.global [%0], [%1], 16;" :: "r"(saddr), "l"(gptr) : "memory")
#define CP_COMMIT() asm volatile("cp.async.commit_group;" ::: "memory")
#define CP_WAIT3()  asm volatile("cp.async.wait_group 3;" ::: "memory")

// ---------------- kernel: fp32 -> fp16 weight conversion (+zero counters) --
__global__ __launch_bounds__(256)
void cvt_f16_kernel(const float4* __restrict__ src, int which, size_t n4) {
    if (which == 1 && blockIdx.x == 0 && threadIdx.x < EE)
        d_counts[threadIdx.x] = 0;
    __half* dstb = (which == 1) ? d_w1h : d_w2h;
    uint2* dst = (uint2*)dstb;
    size_t i  = (size_t)blockIdx.x * blockDim.x + threadIdx.x;
    size_t st = (size_t)gridDim.x * blockDim.x;
    for (; i < n4; i += st) {
        float4 v = src[i];
        __half2 h0 = __floats2half2_rn(v.x, v.y);
        __half2 h1 = __floats2half2_rn(v.z, v.w);
        uint2 o;
        o.x = *(uint32_t*)&h0;
        o.y = *(uint32_t*)&h1;
        dst[i] = o;
    }
}

// ---------------- kernel: router (fp32) + fused x->fp16 + slot record ------
__global__ __launch_bounds__(256)
void router_kernel(const float* __restrict__ x,
                   const float* __restrict__ Wg,
                   float* __restrict__ logits_out) {
    __shared__ float sWg[EE][HH];
    for (int i = threadIdx.x; i < EE * HH; i += blockDim.x)
        sWg[i / HH][i % HH] = Wg[i];
    __syncthreads();

    const int warp = threadIdx.x >> 5;
    const int lane = threadIdx.x & 31;
    const int t = blockIdx.x * 8 + warp;
    if (t >= TT) return;

    const float* xr = x + (size_t)t * HH;

    // fused x -> fp16
    {
        uint2* xo = (uint2*)(d_xh + (size_t)t * HH);
        const float4* xi = (const float4*)xr;
        for (int k4 = lane; k4 < HH / 4; k4 += 32) {
            float4 v = xi[k4];
            __half2 h0 = __floats2half2_rn(v.x, v.y);
            __half2 h1 = __floats2half2_rn(v.z, v.w);
            uint2 o;
            o.x = *(uint32_t*)&h0;
            o.y = *(uint32_t*)&h1;
            xo[k4] = o;
        }
    }

    float acc[EE];
#pragma unroll
    for (int e = 0; e < EE; e++) acc[e] = 0.0f;
    for (int k = lane; k < HH; k += 32) {
        float xv = xr[k];
#pragma unroll
        for (int e = 0; e < EE; e++) acc[e] += xv * sWg[e][k];
    }
#pragma unroll
    for (int off = 16; off > 0; off >>= 1)
#pragma unroll
        for (int e = 0; e < EE; e++)
            acc[e] += __shfl_xor_sync(0xFFFFFFFFu, acc[e], off);

    if (lane == 0) {
        if (logits_out)
#pragma unroll
            for (int e = 0; e < EE; e++) logits_out[(size_t)t * EE + e] = acc[e];
        int i0 = 0; float v0 = acc[0];
#pragma unroll
        for (int e = 1; e < EE; e++) if (acc[e] > v0) { v0 = acc[e]; i0 = e; }
        int i1 = -1; float v1 = -3.4e38f;
#pragma unroll
        for (int e = 0; e < EE; e++)
            if (e != i0 && acc[e] > v1) { v1 = acc[e]; i1 = e; }
        float r  = expf(v1 - v0);
        float w0 = 1.0f / (1.0f + r);
        float w1 = 1.0f - w0;
        int p0 = atomicAdd(&d_counts[i0], 1);
        d_tok[i0 * TT + p0] = t;
        int p1 = atomicAdd(&d_counts[i1], 1);
        d_tok[i1 * TT + p1] = t;
        d_slotEP[t * 2 + 0] = ((uint32_t)i0 << 20) | (uint32_t)p0;
        d_slotEP[t * 2 + 1] = ((uint32_t)i1 << 20) | (uint32_t)p1;
        d_wtok[t * 2 + 0] = w0;
        d_wtok[t * 2 + 1] = w1;
    }
}

// ---------------- GEMM: fp16-acc m16n8k16, 128x128 CTA, 4 warps ----------
// fp16 group accumulators over K=64, promoted to fp32 masters.
constexpr int BM = 128, BN = 128, BK = 32;
constexpr int NT = 128;                            // threads per CTA
constexpr int BKW = 20;                            // padded words/row
constexpr int A_STAGE_B = BM * BKW * 4;            // 10240 B
constexpr int B_STAGE_B = BN * BKW * 4;            // 10240 B
constexpr int STAGE_B   = A_STAGE_B + B_STAGE_B;   // 20480 B
constexpr int NSTAGE    = 5;
constexpr int SMEM_DYN  = NSTAGE * STAGE_B;        // 102400 B (2 CTAs -> 200 KB/SM)

__device__ __forceinline__ void load_frags(uint32_t af[4][4], uint32_t bf[8][2],
                                           const uint32_t aLd[4], const uint32_t bLd[4],
                                           uint32_t ko) {
#pragma unroll
    for (int mf = 0; mf < 4; mf++)
        LDSM_X4(af[mf][0], af[mf][1], af[mf][2], af[mf][3], aLd[mf] + ko);
#pragma unroll
    for (int j = 0; j < 4; j++)
        LDSM_X4(bf[2 * j][0], bf[2 * j][1], bf[2 * j + 1][0], bf[2 * j + 1][1],
                bLd[j] + ko);
}

template <bool FIRST>
__global__ __launch_bounds__(NT, 2)
void moe_gemm_kernel(const float* __restrict__ bias) {
    const int e   = blockIdx.z;
    const int cnt = d_counts[e];
    const int m0  = blockIdx.y * BM;
    if (m0 >= cnt) return;
    const int n0   = blockIdx.x * BN;
    const int KDIM = FIRST ? HH : II;
    const int NDIM = FIRST ? II : HH;
    const int offs = expert_offset(e);
    const int NC   = KDIM / BK;

    extern __shared__ char dynsmem[];
    const uint32_t sbase = smem_u32(dynsmem);

    const int tid = threadIdx.x;
    const __half* Aglob = FIRST ? d_xh : d_hmid;
    const __half* Wt    = FIRST ? d_w1h : d_w2h;

    // cp.async loaders: A 4 chunks/thread, B 4 chunks/thread (16B each)
    const __half* aG[4]; uint32_t aSoff[4];
#pragma unroll
    for (int j = 0; j < 4; j++) {
        int idx = tid + j * NT;
        int row = idx >> 2, c = idx & 3;
        int gm = m0 + row;
        if (gm >= cnt) gm = cnt - 1;
        size_t rowoff;
        if (FIRST) rowoff = (size_t)d_tok[e * TT + gm] * HH;
        else       rowoff = (size_t)(offs + gm) * II;
        aG[j]    = Aglob + rowoff + c * 8;
        aSoff[j] = row * (BKW * 4) + c * 16;
    }
    const __half* bG[4]; uint32_t bSoff[4];
#pragma unroll
    for (int j = 0; j < 4; j++) {
        int idx = tid + j * NT;
        int row = idx >> 2, c = idx & 3;
        bG[j]    = Wt + (size_t)e * ((size_t)II * HH) + (size_t)(n0 + row) * KDIM + c * 8;
        bSoff[j] = A_STAGE_B + row * (BKW * 4) + c * 16;
    }

    // prologue: stages 0..3
#pragma unroll
    for (int s = 0; s < NSTAGE - 1; s++) {
        uint32_t so = sbase + s * STAGE_B;
#pragma unroll
        for (int j = 0; j < 4; j++) CP_ASYNC16(so + aSoff[j], aG[j] + s * BK);
#pragma unroll
        for (int j = 0; j < 4; j++) CP_ASYNC16(so + bSoff[j], bG[j] + s * BK);
        CP_COMMIT();
    }

    const int wid = tid >> 5, lane = tid & 31;
    const int wm = (wid >> 1) * 64;       // 2 m-warps
    const int wn = (wid & 1) * 64;        // 2 n-warps
    const int g = lane >> 2, tg = lane & 3;

    // ldmatrix per-lane base addresses
    uint32_t aLd[4];
#pragma unroll
    for (int mf = 0; mf < 4; mf++) {
        int row = wm + mf * 16 + (lane & 7) + ((lane >> 3) & 1) * 8;
        int col = ((lane >> 4) & 1) * 16;
        aLd[mf] = sbase + row * (BKW * 4) + col;
    }
    uint32_t bLd[4];
#pragma unroll
    for (int nf2 = 0; nf2 < 4; nf2++) {
        int row = wn + nf2 * 16 + (lane & 7) + ((lane >> 4) & 1) * 8;
        int col = ((lane >> 3) & 1) * 16;
        bLd[nf2] = sbase + A_STAGE_B + row * (BKW * 4) + col;
    }

    float acc[4][8][4];                 // fp32 masters
#pragma unroll
    for (int a = 0; a < 4; a++)
#pragma unroll
        for (int b = 0; b < 8; b++)
#pragma unroll
            for (int c = 0; c < 4; c++) acc[a][b][c] = 0.0f;

    uint32_t acch[4][8][2];             // fp16x2 group accumulators
    uint32_t af[4][4], bf[8][2];

    CP_WAIT3();
    __syncthreads();

    int stage = 0;
    const int NG = NC / 2;              // K=64 groups
    for (int grp = 0; grp < NG; grp++) {
#pragma unroll
        for (int half = 0; half < 2; half++) {
            const int i = grp * 2 + half;
            const uint32_t stoff = stage * STAGE_B;

            // kk0
            load_frags(af, bf, aLd, bLd, stoff);
            if (half == 0) {
#pragma unroll
                for (int mf = 0; mf < 4; mf++)
#pragma unroll
                    for (int nf = 0; nf < 8; nf++)
                        MMA_F16Z(acch[mf][nf], af[mf], bf[nf]);
            } else {
#pragma unroll
                for (int mf = 0; mf < 4; mf++)
#pragma unroll
                    for (int nf = 0; nf < 8; nf++)
                        MMA_F16H(acch[mf][nf], af[mf], bf[nf]);
            }
            // kk1
            load_frags(af, bf, aLd, bLd, stoff + 32);
#pragma unroll
            for (int mf = 0; mf < 4; mf++)
#pragma unroll
                for (int nf = 0; nf < 8; nf++)
                    MMA_F16H(acch[mf][nf], af[mf], bf[nf]);

            // prefetch chunk i+4
            const int nx = i + NSTAGE - 1;
            if (nx < NC) {
                int s = nx % NSTAGE;
                uint32_t so = sbase + s * STAGE_B;
#pragma unroll
                for (int j = 0; j < 4; j++) CP_ASYNC16(so + aSoff[j], aG[j] + nx * BK);
#pragma unroll
                for (int j = 0; j < 4; j++) CP_ASYNC16(so + bSoff[j], bG[j] + nx * BK);
            }
            CP_COMMIT();

            // promote at group end (hides in cp.async latency, before wait)
            if (half == 1) {
#pragma unroll
                for (int mf = 0; mf < 4; mf++)
#pragma unroll
                    for (int nf = 0; nf < 8; nf++) {
#pragma unroll
                        for (int d = 0; d < 2; d++) {
                            __half2 h = *(__half2*)&acch[mf][nf][d];
                            float2 f = __half22float2(h);
                            acc[mf][nf][2 * d + 0] += f.x;
                            acc[mf][nf][2 * d + 1] += f.y;
                        }
                    }
            }

            if (i + 1 < NC) {
                CP_WAIT3();
                __syncthreads();
            }
            stage = (stage + 1 == NSTAGE) ? 0 : stage + 1;
        }
    }

    // epilogue (acc: d0,d1 = row g cols 2tg,2tg+1; d2,d3 = row g+8)
#pragma unroll
    for (int mf = 0; mf < 4; mf++) {
#pragma unroll
        for (int half = 0; half < 2; half++) {
            int m = m0 + wm + mf * 16 + g + half * 8;
            if (m >= cnt) continue;
            if (FIRST) {
                __half* dst = d_hmid + (size_t)(offs + m) * II + n0;
#pragma unroll
                for (int nf = 0; nf < 8; nf++) {
                    int col = wn + nf * 8 + tg * 2;
                    float bb0 = bias[(size_t)e * NDIM + n0 + col];
                    float bb1 = bias[(size_t)e * NDIM + n0 + col + 1];
                    float s0 = silu_f(acc[mf][nf][half * 2 + 0] + bb0);
                    float s1 = silu_f(acc[mf][nf][half * 2 + 1] + bb1);
                    *(__half2*)(dst + col) = __floats2half2_rn(s0, s1);
                }
            } else {
                float* dst = d_osc + (size_t)(offs + m) * HH + n0;
#pragma unroll
                for (int nf = 0; nf < 8; nf++) {
                    int col = wn + nf * 8 + tg * 2;
                    float bb0 = bias[(size_t)e * NDIM + n0 + col];
                    float bb1 = bias[(size_t)e * NDIM + n0 + col + 1];
                    *(float2*)(dst + col) = make_float2(acc[mf][nf][half * 2 + 0] + bb0,
                                                        acc[mf][nf][half * 2 + 1] + bb1);
                }
            }
        }
    }
}

// ---------------- kernel: combine two expert rows per token ----------------
__global__ __launch_bounds__(256)
void combine_kernel(float* __restrict__ out) {
    const int t = blockIdx.x;
    const uint32_t s0 = d_slotEP[t * 2 + 0];
    const uint32_t s1 = d_slotEP[t * 2 + 1];
    const int e0 = (int)(s0 >> 20), p0 = (int)(s0 & 0xFFFFFu);
    const int e1 = (int)(s1 >> 20), p1 = (int)(s1 & 0xFFFFFu);
    const float w0 = d_wtok[t * 2 + 0];
    const float w1 = d_wtok[t * 2 + 1];
    const size_t r0 = (size_t)(expert_offset(e0) + p0) * HH;
    const size_t r1 = (size_t)(expert_offset(e1) + p1) * HH;
    const float4* a = (const float4*)(d_osc + r0);
    const float4* b = (const float4*)(d_osc + r1);
    float4* o = (float4*)(out + (size_t)t * HH);
    const int k = threadIdx.x;           // 256 threads x float4 = 1024
    float4 va = a[k], vb = b[k];
    float4 vo;
    vo.x = w0 * va.x + w1 * vb.x;
    vo.y = w0 * va.y + w1 * vb.y;
    vo.z = w0 * va.z + w1 * vb.z;
    vo.w = w0 * va.w + w1 * vb.w;
    o[k] = vo;
}

// ---------------- launch ----------------
extern "C" void kernel_launch(void* const* d_in, const int* in_sizes, int n_in,
                              void* d_out, int out_size) {
    const float* x  = (const float*)d_in[0];   // [T,H]
    const float* Wg = (const float*)d_in[1];   // [E,H]
    const float* W1 = (const float*)d_in[2];   // [E,I,H]
    const float* b1 = (const float*)d_in[3];   // [E,I]
    const float* W2 = (const float*)d_in[4];   // [E,H,I]
    const float* b2 = (const float*)d_in[5];   // [E,H]
    float* out = (float*)d_out;

    float* logits = nullptr;
    if ((size_t)out_size >= (size_t)TT * HH + (size_t)TT * EE)
        logits = out + (size_t)TT * HH;

    cudaFuncSetAttribute(moe_gemm_kernel<true>,  cudaFuncAttributeMaxDynamicSharedMemorySize, SMEM_DYN);
    cudaFuncSetAttribute(moe_gemm_kernel<false>, cudaFuncAttributeMaxDynamicSharedMemorySize, SMEM_DYN);

    cvt_f16_kernel<<<4096, 256>>>((const float4*)W1, 1, (size_t)EE * II * HH / 4);  // zeroes counts
    cvt_f16_kernel<<<4096, 256>>>((const float4*)W2, 2, (size_t)EE * HH * II / 4);
    router_kernel<<<TT / 8, 256>>>(x, Wg, logits);   // also writes d_xh + slots

    dim3 g1(II / BN, TT / BM, EE);   // (32, 128, 8) -- 4th launch: ncu profiles this
    moe_gemm_kernel<true><<<g1, NT, SMEM_DYN>>>(b1);

    dim3 g2(HH / BN, TT / BM, EE);   // (8, 128, 8)
    moe_gemm_kernel<false><<<g2, NT, SMEM_DYN>>>(b2);

    combine_kernel<<<TT, 256>>>(out);
}

// round 14
// speedup vs baseline: 1.5832x; 1.5832x over previous
#include <cuda_runtime.h>
#include <cuda_fp16.h>
#include <cstdint>

// Problem constants
#define TT 16384   // B*S tokens
#define HH 1024    // hidden
#define II 4096    // intermediate
#define EE 8       // experts

// ---------------- scratch (device globals; no runtime allocation) ----------
__device__ int      d_counts[EE];
__device__ int      d_tok[EE * TT];
__device__ uint32_t d_slotEP[2 * TT];             // (expert<<20)|pos per token slot
__device__ float    d_wtok[2 * TT];               // per-token top-2 weights
__device__ __half   d_hmid[(size_t)2 * TT * II];  // fp16 intermediate (268 MB)
__device__ float    d_osc[(size_t)2 * TT * HH];   // fp32 expert outputs (134 MB)
__device__ __half   d_xh[(size_t)TT * HH];        // fp16 x (written by router)
__device__ __half   d_w1h[(size_t)EE * II * HH];  // fp16 W1
__device__ __half   d_w2h[(size_t)EE * HH * II];  // fp16 W2

// ---------------- helpers ----------------
__device__ __forceinline__ float silu_f(float v) { return v / (1.0f + __expf(-v)); }
__device__ __forceinline__ uint32_t smem_u32(const void* p) {
    uint32_t a;
    asm("{ .reg .u64 t; cvta.to.shared.u64 t, %1; cvt.u32.u64 %0, t; }" : "=r"(a) : "l"(p));
    return a;
}
__device__ __forceinline__ int expert_offset(int e) {
    int off = 0;
#pragma unroll
    for (int q = 0; q < EE; q++) off += (q < e) ? d_counts[q] : 0;
    return off;
}

// fp16-accumulate MMA, accumulating variant
#define MMA_F16H(Dh, A, B_)                                                      \
    asm volatile(                                                                \
        "mma.sync.aligned.m16n8k16.row.col.f16.f16.f16.f16 "                     \
        "{%0,%1}, {%2,%3,%4,%5}, {%6,%7}, {%0,%1};\n"                            \
        : "+r"((Dh)[0]), "+r"((Dh)[1])                                           \
        : "r"((A)[0]), "r"((A)[1]), "r"((A)[2]), "r"((A)[3]),                    \
          "r"((B_)[0]), "r"((B_)[1]))

// fp16-accumulate MMA, zero-C variant (group start)
#define MMA_F16Z(Dh, A, B_)                                                      \
    asm volatile(                                                                \
        "mma.sync.aligned.m16n8k16.row.col.f16.f16.f16.f16 "                     \
        "{%0,%1}, {%2,%3,%4,%5}, {%6,%7}, {%8,%9};\n"                            \
        : "=r"((Dh)[0]), "=r"((Dh)[1])                                           \
        : "r"((A)[0]), "r"((A)[1]), "r"((A)[2]), "r"((A)[3]),                    \
          "r"((B_)[0]), "r"((B_)[1]), "r"(0u), "r"(0u))

#define LDSM_X4(r0, r1, r2, r3, addr)                                            \
    asm volatile("ldmatrix.sync.aligned.m8n8.x4.shared.b16 {%0,%1,%2,%3}, [%4];" \
        : "=r"(r0), "=r"(r1), "=r"(r2), "=r"(r3) : "r"(addr))

#define CP_ASYNC16(saddr, gptr) \
    asm volatile("cp.async.cg.shared.global [%0], [%1], 16;" :: "r"(saddr), "l"(gptr) : "memory")
#define CP_COMMIT() asm volatile("cp.async.commit_group;" ::: "memory")
#define CP_WAIT3()  asm volatile("cp.async.wait_group 3;" ::: "memory")

// ---------------- kernel: fp32 -> fp16 weight conversion (+zero counters) --
__global__ __launch_bounds__(256)
void cvt_f16_kernel(const float4* __restrict__ src, int which, size_t n4) {
    if (which == 1 && blockIdx.x == 0 && threadIdx.x < EE)
        d_counts[threadIdx.x] = 0;
    __half* dstb = (which == 1) ? d_w1h : d_w2h;
    uint2* dst = (uint2*)dstb;
    size_t i  = (size_t)blockIdx.x * blockDim.x + threadIdx.x;
    size_t st = (size_t)gridDim.x * blockDim.x;
    for (; i < n4; i += st) {
        float4 v = src[i];
        __half2 h0 = __floats2half2_rn(v.x, v.y);
        __half2 h1 = __floats2half2_rn(v.z, v.w);
        uint2 o;
        o.x = *(uint32_t*)&h0;
        o.y = *(uint32_t*)&h1;
        dst[i] = o;
    }
}

// ---------------- kernel: router (fp32) + fused x->fp16 + slot record ------
__global__ __launch_bounds__(256)
void router_kernel(const float* __restrict__ x,
                   const float* __restrict__ Wg,
                   float* __restrict__ logits_out) {
    __shared__ float sWg[EE][HH];
    for (int i = threadIdx.x; i < EE * HH; i += blockDim.x)
        sWg[i / HH][i % HH] = Wg[i];
    __syncthreads();

    const int warp = threadIdx.x >> 5;
    const int lane = threadIdx.x & 31;
    const int t = blockIdx.x * 8 + warp;
    if (t >= TT) return;

    const float* xr = x + (size_t)t * HH;

    // fused x -> fp16
    {
        uint2* xo = (uint2*)(d_xh + (size_t)t * HH);
        const float4* xi = (const float4*)xr;
        for (int k4 = lane; k4 < HH / 4; k4 += 32) {
            float4 v = xi[k4];
            __half2 h0 = __floats2half2_rn(v.x, v.y);
            __half2 h1 = __floats2half2_rn(v.z, v.w);
            uint2 o;
            o.x = *(uint32_t*)&h0;
            o.y = *(uint32_t*)&h1;
            xo[k4] = o;
        }
    }

    float acc[EE];
#pragma unroll
    for (int e = 0; e < EE; e++) acc[e] = 0.0f;
    for (int k = lane; k < HH; k += 32) {
        float xv = xr[k];
#pragma unroll
        for (int e = 0; e < EE; e++) acc[e] += xv * sWg[e][k];
    }
#pragma unroll
    for (int off = 16; off > 0; off >>= 1)
#pragma unroll
        for (int e = 0; e < EE; e++)
            acc[e] += __shfl_xor_sync(0xFFFFFFFFu, acc[e], off);

    if (lane == 0) {
        if (logits_out)
#pragma unroll
            for (int e = 0; e < EE; e++) logits_out[(size_t)t * EE + e] = acc[e];
        int i0 = 0; float v0 = acc[0];
#pragma unroll
        for (int e = 1; e < EE; e++) if (acc[e] > v0) { v0 = acc[e]; i0 = e; }
        int i1 = -1; float v1 = -3.4e38f;
#pragma unroll
        for (int e = 0; e < EE; e++)
            if (e != i0 && acc[e] > v1) { v1 = acc[e]; i1 = e; }
        float r  = expf(v1 - v0);
        float w0 = 1.0f / (1.0f + r);
        float w1 = 1.0f - w0;
        int p0 = atomicAdd(&d_counts[i0], 1);
        d_tok[i0 * TT + p0] = t;
        int p1 = atomicAdd(&d_counts[i1], 1);
        d_tok[i1 * TT + p1] = t;
        d_slotEP[t * 2 + 0] = ((uint32_t)i0 << 20) | (uint32_t)p0;
        d_slotEP[t * 2 + 1] = ((uint32_t)i1 << 20) | (uint32_t)p1;
        d_wtok[t * 2 + 0] = w0;
        d_wtok[t * 2 + 1] = w1;
    }
}

// ---------------- GEMM: fp16-acc m16n8k16, 128x128 CTA, 4 warps ----------
// fp16 group accumulators over K=64, promoted to fp32 masters.
// Register-lean addressing: bases + constant strides, recomputed store addrs.
constexpr int BM = 128, BN = 128, BK = 32;
constexpr int NT = 128;                            // threads per CTA
constexpr int BKW = 20;                            // padded words/row
constexpr int ROWB = BKW * 4;                      // 80 B per row
constexpr int A_STAGE_B = BM * ROWB;               // 10240 B
constexpr int B_STAGE_B = BN * ROWB;               // 10240 B
constexpr int STAGE_B   = A_STAGE_B + B_STAGE_B;   // 20480 B
constexpr int NSTAGE    = 5;
constexpr int SMEM_DYN  = NSTAGE * STAGE_B;        // 102400 B (2 CTAs -> 200 KB/SM)

__device__ __forceinline__ void load_frags(uint32_t af[4][4], uint32_t bf[8][2],
                                           const uint32_t aLd[4], const uint32_t bLd[4],
                                           uint32_t ko) {
#pragma unroll
    for (int mf = 0; mf < 4; mf++)
        LDSM_X4(af[mf][0], af[mf][1], af[mf][2], af[mf][3], aLd[mf] + ko);
#pragma unroll
    for (int j = 0; j < 4; j++)
        LDSM_X4(bf[2 * j][0], bf[2 * j][1], bf[2 * j + 1][0], bf[2 * j + 1][1],
                bLd[j] + ko);
}

template <bool FIRST>
__global__ __launch_bounds__(NT, 2)
void moe_gemm_kernel(const float* __restrict__ bias) {
    const int e   = blockIdx.z;
    const int cnt = d_counts[e];
    const int m0  = blockIdx.y * BM;
    if (m0 >= cnt) return;
    const int n0   = blockIdx.x * BN;
    constexpr int KDIM = FIRST ? HH : II;
    constexpr int NDIM = FIRST ? II : HH;
    const int offs = expert_offset(e);
    constexpr int NC = KDIM / BK;

    extern __shared__ char dynsmem[];
    const uint32_t sbase = smem_u32(dynsmem);

    const int tid = threadIdx.x;
    const int ldrow = tid >> 2;          // 0..31
    const int ldc16 = (tid & 3) * 16;    // byte offset of 16B chunk in row

    // A source: FIRST -> 4 uint32 element-offsets into d_xh (gather);
    //           !FIRST -> single base pointer + constant row strides.
    uint32_t aOff0 = 0;                  // FIRST only
    uint32_t aOff[4];
    const __half* aBase;
    if (FIRST) {
        aBase = d_xh;
#pragma unroll
        for (int j = 0; j < 4; j++) {
            int gm = m0 + ldrow + j * 32;
            if (gm >= cnt) gm = cnt - 1;
            aOff[j] = (uint32_t)d_tok[e * TT + gm] * HH + (tid & 3) * 8;
        }
        (void)aOff0;
    } else {
        int gm = m0 + ldrow;
        int gmax = cnt - 1;
        // rows j*32 apart; clamp each
#pragma unroll
        for (int j = 0; j < 4; j++) {
            int r = gm + j * 32; if (r > gmax) r = gmax;
            aOff[j] = (uint32_t)(offs + r);   // row index; scaled at use
        }
        aBase = d_hmid;
    }
    // B source: single base + constant strides (32 rows apart)
    const __half* bBase = (FIRST ? d_w1h : d_w2h)
        + (size_t)e * ((size_t)II * HH) + (size_t)(n0 + ldrow) * KDIM + (tid & 3) * 8;

    // smem store bases (stage 0); row strides are compile-time constants
    const uint32_t aSt0 = sbase + ldrow * ROWB + ldc16;
    const uint32_t bSt0 = sbase + A_STAGE_B + ldrow * ROWB + ldc16;

    // prologue: stages 0..3
#pragma unroll
    for (int s = 0; s < NSTAGE - 1; s++) {
        const uint32_t so = (uint32_t)(s * STAGE_B);
#pragma unroll
        for (int j = 0; j < 4; j++) {
            const __half* src = FIRST
                ? aBase + aOff[j] + s * BK
                : aBase + (size_t)aOff[j] * II + (tid & 3) * 8 + s * BK;
            CP_ASYNC16(aSt0 + so + j * (32 * ROWB), src);
        }
#pragma unroll
        for (int j = 0; j < 4; j++)
            CP_ASYNC16(bSt0 + so + j * (32 * ROWB),
                       bBase + (size_t)j * 32 * KDIM + s * BK);
        CP_COMMIT();
    }

    const int wid = tid >> 5, lane = tid & 31;
    const int wm = (wid >> 1) * 64;       // 2 m-warps
    const int wn = (wid & 1) * 64;        // 2 n-warps
    const int g = lane >> 2, tg = lane & 3;

    // ldmatrix per-lane base addresses
    uint32_t aLd[4];
#pragma unroll
    for (int mf = 0; mf < 4; mf++) {
        int row = wm + mf * 16 + (lane & 7) + ((lane >> 3) & 1) * 8;
        int col = ((lane >> 4) & 1) * 16;
        aLd[mf] = sbase + row * ROWB + col;
    }
    uint32_t bLd[4];
#pragma unroll
    for (int nf2 = 0; nf2 < 4; nf2++) {
        int row = wn + nf2 * 16 + (lane & 7) + ((lane >> 4) & 1) * 8;
        int col = ((lane >> 3) & 1) * 16;
        bLd[nf2] = sbase + A_STAGE_B + row * ROWB + col;
    }

    float acc[4][8][4];                 // fp32 masters
#pragma unroll
    for (int a = 0; a < 4; a++)
#pragma unroll
        for (int b = 0; b < 8; b++)
#pragma unroll
            for (int c = 0; c < 4; c++) acc[a][b][c] = 0.0f;

    uint32_t acch[4][8][2];             // fp16x2 group accumulators
    uint32_t af[4][4], bf[8][2];

    CP_WAIT3();
    __syncthreads();

    int stage = 0;
#pragma unroll 1
    for (int grp = 0; grp < NC / 2; grp++) {
#pragma unroll
        for (int half = 0; half < 2; half++) {
            const int i = grp * 2 + half;
            const uint32_t stoff = (uint32_t)(stage * STAGE_B);

            // kk0
            load_frags(af, bf, aLd, bLd, stoff);
            if (half == 0) {
#pragma unroll
                for (int mf = 0; mf < 4; mf++)
#pragma unroll
                    for (int nf = 0; nf < 8; nf++)
                        MMA_F16Z(acch[mf][nf], af[mf], bf[nf]);
            } else {
#pragma unroll
                for (int mf = 0; mf < 4; mf++)
#pragma unroll
                    for (int nf = 0; nf < 8; nf++)
                        MMA_F16H(acch[mf][nf], af[mf], bf[nf]);
            }
            // kk1
            load_frags(af, bf, aLd, bLd, stoff + 32);
#pragma unroll
            for (int mf = 0; mf < 4; mf++)
#pragma unroll
                for (int nf = 0; nf < 8; nf++)
                    MMA_F16H(acch[mf][nf], af[mf], bf[nf]);

            // prefetch chunk i+4
            const int nx = i + NSTAGE - 1;
            if (nx < NC) {
                int s = stage - 1; if (s < 0) s = NSTAGE - 1;   // (i+4) mod 5
                const uint32_t so = (uint32_t)(s * STAGE_B);
#pragma unroll
                for (int j = 0; j < 4; j++) {
                    const __half* src = FIRST
                        ? aBase + aOff[j] + nx * BK
                        : aBase + (size_t)aOff[j] * II + (tid & 3) * 8 + nx * BK;
                    CP_ASYNC16(aSt0 + so + j * (32 * ROWB), src);
                }
#pragma unroll
                for (int j = 0; j < 4; j++)
                    CP_ASYNC16(bSt0 + so + j * (32 * ROWB),
                               bBase + (size_t)j * 32 * KDIM + nx * BK);
            }
            CP_COMMIT();

            // promote at group end (hides in cp.async latency, before wait)
            if (half == 1) {
#pragma unroll
                for (int mf = 0; mf < 4; mf++)
#pragma unroll
                    for (int nf = 0; nf < 8; nf++) {
#pragma unroll
                        for (int d = 0; d < 2; d++) {
                            float2 f = __half22float2(*(__half2*)&acch[mf][nf][d]);
                            acc[mf][nf][2 * d + 0] += f.x;
                            acc[mf][nf][2 * d + 1] += f.y;
                        }
                    }
            }

            if (i + 1 < NC) {
                CP_WAIT3();
                __syncthreads();
            }
            stage = (stage + 1 == NSTAGE) ? 0 : stage + 1;
        }
    }

    // epilogue (acc: d0,d1 = row g cols 2tg,2tg+1; d2,d3 = row g+8)
#pragma unroll
    for (int mf = 0; mf < 4; mf++) {
#pragma unroll
        for (int half = 0; half < 2; half++) {
            int m = m0 + wm + mf * 16 + g + half * 8;
            if (m >= cnt) continue;
            if (FIRST) {
                __half* dst = d_hmid + (size_t)(offs + m) * II + n0;
#pragma unroll
                for (int nf = 0; nf < 8; nf++) {
                    int col = wn + nf * 8 + tg * 2;
                    float bb0 = bias[(size_t)e * NDIM + n0 + col];
                    float bb1 = bias[(size_t)e * NDIM + n0 + col + 1];
                    float s0 = silu_f(acc[mf][nf][half * 2 + 0] + bb0);
                    float s1 = silu_f(acc[mf][nf][half * 2 + 1] + bb1);
                    *(__half2*)(dst + col) = __floats2half2_rn(s0, s1);
                }
            } else {
                float* dst = d_osc + (size_t)(offs + m) * HH + n0;
#pragma unroll
                for (int nf = 0; nf < 8; nf++) {
                    int col = wn + nf * 8 + tg * 2;
                    float bb0 = bias[(size_t)e * NDIM + n0 + col];
                    float bb1 = bias[(size_t)e * NDIM + n0 + col + 1];
                    *(float2*)(dst + col) = make_float2(acc[mf][nf][half * 2 + 0] + bb0,
                                                        acc[mf][nf][half * 2 + 1] + bb1);
                }
            }
        }
    }
}

// ---------------- kernel: combine two expert rows per token ----------------
__global__ __launch_bounds__(256)
void combine_kernel(float* __restrict__ out) {
    const int t = blockIdx.x;
    const uint32_t s0 = d_slotEP[t * 2 + 0];
    const uint32_t s1 = d_slotEP[t * 2 + 1];
    const int e0 = (int)(s0 >> 20), p0 = (int)(s0 & 0xFFFFFu);
    const int e1 = (int)(s1 >> 20), p1 = (int)(s1 & 0xFFFFFu);
    const float w0 = d_wtok[t * 2 + 0];
    const float w1 = d_wtok[t * 2 + 1];
    const size_t r0 = (size_t)(expert_offset(e0) + p0) * HH;
    const size_t r1 = (size_t)(expert_offset(e1) + p1) * HH;
    const float4* a = (const float4*)(d_osc + r0);
    const float4* b = (const float4*)(d_osc + r1);
    float4* o = (float4*)(out + (size_t)t * HH);
    const int k = threadIdx.x;           // 256 threads x float4 = 1024
    float4 va = a[k], vb = b[k];
    float4 vo;
    vo.x = w0 * va.x + w1 * vb.x;
    vo.y = w0 * va.y + w1 * vb.y;
    vo.z = w0 * va.z + w1 * vb.z;
    vo.w = w0 * va.w + w1 * vb.w;
    o[k] = vo;
}

// ---------------- launch ----------------
extern "C" void kernel_launch(void* const* d_in, const int* in_sizes, int n_in,
                              void* d_out, int out_size) {
    const float* x  = (const float*)d_in[0];   // [T,H]
    const float* Wg = (const float*)d_in[1];   // [E,H]
    const float* W1 = (const float*)d_in[2];   // [E,I,H]
    const float* b1 = (const float*)d_in[3];   // [E,I]
    const float* W2 = (const float*)d_in[4];   // [E,H,I]
    const float* b2 = (const float*)d_in[5];   // [E,H]
    float* out = (float*)d_out;

    float* logits = nullptr;
    if ((size_t)out_size >= (size_t)TT * HH + (size_t)TT * EE)
        logits = out + (size_t)TT * HH;

    cudaFuncSetAttribute(moe_gemm_kernel<true>,  cudaFuncAttributeMaxDynamicSharedMemorySize, SMEM_DYN);
    cudaFuncSetAttribute(moe_gemm_kernel<false>, cudaFuncAttributeMaxDynamicSharedMemorySize, SMEM_DYN);

    cvt_f16_kernel<<<4096, 256>>>((const float4*)W1, 1, (size_t)EE * II * HH / 4);  // zeroes counts
    cvt_f16_kernel<<<4096, 256>>>((const float4*)W2, 2, (size_t)EE * HH * II / 4);
    router_kernel<<<TT / 8, 256>>>(x, Wg, logits);   // also writes d_xh + slots

    dim3 g1(II / BN, TT / BM, EE);   // (32, 128, 8) -- 4th launch: ncu profiles this
    moe_gemm_kernel<true><<<g1, NT, SMEM_DYN>>>(b1);

    dim3 g2(HH / BN, TT / BM, EE);   // (8, 128, 8)
    moe_gemm_kernel<false><<<g2, NT, SMEM_DYN>>>(b2);

    combine_kernel<<<TT, 256>>>(out);
}

// round 16
// speedup vs baseline: 1.5994x; 1.0102x over previous
#include <cuda_runtime.h>
#include <cuda_fp16.h>
#include <cstdint>

// Problem constants
#define TT 16384   // B*S tokens
#define HH 1024    // hidden
#define II 4096    // intermediate
#define EE 8       // experts

// ---------------- scratch (device globals; no runtime allocation) ----------
__device__ int      d_counts[EE];
__device__ int      d_tok[EE * TT];
__device__ uint32_t d_slotEP[2 * TT];             // (expert<<20)|pos per token slot
__device__ float    d_wtok[2 * TT];               // per-token top-2 weights
// +128 pad rows: unclamped tail reads of the last tile stay in-bounds
__device__ __half   d_hmid[(size_t)(2 * TT + 128) * II];
__device__ float    d_osc[(size_t)2 * TT * HH];   // fp32 expert outputs (134 MB)
__device__ __half   d_xh[(size_t)TT * HH];        // fp16 x (written by router)
__device__ __half   d_w1h[(size_t)EE * II * HH];  // fp16 W1
__device__ __half   d_w2h[(size_t)EE * HH * II];  // fp16 W2

// ---------------- helpers ----------------
__device__ __forceinline__ float silu_f(float v) { return v / (1.0f + __expf(-v)); }
__device__ __forceinline__ uint32_t smem_u32(const void* p) {
    uint32_t a;
    asm("{ .reg .u64 t; cvta.to.shared.u64 t, %1; cvt.u32.u64 %0, t; }" : "=r"(a) : "l"(p));
    return a;
}
__device__ __forceinline__ int expert_offset(int e) {
    int off = 0;
#pragma unroll
    for (int q = 0; q < EE; q++) off += (q < e) ? d_counts[q] : 0;
    return off;
}

// fp16-accumulate MMA, accumulating variant (B pair passed as 2 regs)
#define MMA_F16H(Dh, A, b0, b1)                                                  \
    asm volatile(                                                                \
        "mma.sync.aligned.m16n8k16.row.col.f16.f16.f16.f16 "                     \
        "{%0,%1}, {%2,%3,%4,%5}, {%6,%7}, {%0,%1};\n"                            \
        : "+r"((Dh)[0]), "+r"((Dh)[1])                                           \
        : "r"((A)[0]), "r"((A)[1]), "r"((A)[2]), "r"((A)[3]),                    \
          "r"(b0), "r"(b1))

// fp16-accumulate MMA, zero-C variant (group start)
#define MMA_F16Z(Dh, A, b0, b1)                                                  \
    asm volatile(                                                                \
        "mma.sync.aligned.m16n8k16.row.col.f16.f16.f16.f16 "                     \
        "{%0,%1}, {%2,%3,%4,%5}, {%6,%7}, {%8,%9};\n"                            \
        : "=r"((Dh)[0]), "=r"((Dh)[1])                                           \
        : "r"((A)[0]), "r"((A)[1]), "r"((A)[2]), "r"((A)[3]),                    \
          "r"(b0), "r"(b1), "r"(0u), "r"(0u))

// ldmatrix with compile-time byte offset via template parameter
template <int OFF>
__device__ __forceinline__ void ldsm_off(uint32_t& r0, uint32_t& r1,
                                         uint32_t& r2, uint32_t& r3,
                                         uint32_t addr) {
    asm volatile("ldmatrix.sync.aligned.m8n8.x4.shared.b16 {%0,%1,%2,%3}, [%4+%5];"
        : "=r"(r0), "=r"(r1), "=r"(r2), "=r"(r3) : "r"(addr), "n"(OFF));
}

#define CP_ASYNC16(saddr, gptr) \
    asm volatile("cp.async.cg.shared.global [%0], [%1], 16;" :: "r"(saddr), "l"(gptr) : "memory")
#define CP_COMMIT() asm volatile("cp.async.commit_group;" ::: "memory")
#define CP_WAIT3()  asm volatile("cp.async.wait_group 3;" ::: "memory")

// ---------------- kernel: fp32 -> fp16 weight conversion (+zero counters) --
__global__ __launch_bounds__(256)
void cvt_f16_kernel(const float4* __restrict__ src, int which, size_t n4) {
    if (which == 1 && blockIdx.x == 0 && threadIdx.x < EE)
        d_counts[threadIdx.x] = 0;
    __half* dstb = (which == 1) ? d_w1h : d_w2h;
    uint2* dst = (uint2*)dstb;
    size_t i  = (size_t)blockIdx.x * blockDim.x + threadIdx.x;
    size_t st = (size_t)gridDim.x * blockDim.x;
    for (; i < n4; i += st) {
        float4 v = src[i];
        __half2 h0 = __floats2half2_rn(v.x, v.y);
        __half2 h1 = __floats2half2_rn(v.z, v.w);
        uint2 o;
        o.x = *(uint32_t*)&h0;
        o.y = *(uint32_t*)&h1;
        dst[i] = o;
    }
}

// ---------------- kernel: router (fp32) + fused x->fp16 + slot record ------
__global__ __launch_bounds__(256)
void router_kernel(const float* __restrict__ x,
                   const float* __restrict__ Wg,
                   float* __restrict__ logits_out) {
    __shared__ float sWg[EE][HH];
    for (int i = threadIdx.x; i < EE * HH; i += blockDim.x)
        sWg[i / HH][i % HH] = Wg[i];
    __syncthreads();

    const int warp = threadIdx.x >> 5;
    const int lane = threadIdx.x & 31;
    const int t = blockIdx.x * 8 + warp;
    if (t >= TT) return;

    const float* xr = x + (size_t)t * HH;

    // fused x -> fp16
    {
        uint2* xo = (uint2*)(d_xh + (size_t)t * HH);
        const float4* xi = (const float4*)xr;
        for (int k4 = lane; k4 < HH / 4; k4 += 32) {
            float4 v = xi[k4];
            __half2 h0 = __floats2half2_rn(v.x, v.y);
            __half2 h1 = __floats2half2_rn(v.z, v.w);
            uint2 o;
            o.x = *(uint32_t*)&h0;
            o.y = *(uint32_t*)&h1;
            xo[k4] = o;
        }
    }

    float acc[EE];
#pragma unroll
    for (int e = 0; e < EE; e++) acc[e] = 0.0f;
    for (int k = lane; k < HH; k += 32) {
        float xv = xr[k];
#pragma unroll
        for (int e = 0; e < EE; e++) acc[e] += xv * sWg[e][k];
    }
#pragma unroll
    for (int off = 16; off > 0; off >>= 1)
#pragma unroll
        for (int e = 0; e < EE; e++)
            acc[e] += __shfl_xor_sync(0xFFFFFFFFu, acc[e], off);

    if (lane == 0) {
        if (logits_out)
#pragma unroll
            for (int e = 0; e < EE; e++) logits_out[(size_t)t * EE + e] = acc[e];
        int i0 = 0; float v0 = acc[0];
#pragma unroll
        for (int e = 1; e < EE; e++) if (acc[e] > v0) { v0 = acc[e]; i0 = e; }
        int i1 = -1; float v1 = -3.4e38f;
#pragma unroll
        for (int e = 0; e < EE; e++)
            if (e != i0 && acc[e] > v1) { v1 = acc[e]; i1 = e; }
        float r  = expf(v1 - v0);
        float w0 = 1.0f / (1.0f + r);
        float w1 = 1.0f - w0;
        int p0 = atomicAdd(&d_counts[i0], 1);
        d_tok[i0 * TT + p0] = t;
        int p1 = atomicAdd(&d_counts[i1], 1);
        d_tok[i1 * TT + p1] = t;
        d_slotEP[t * 2 + 0] = ((uint32_t)i0 << 20) | (uint32_t)p0;
        d_slotEP[t * 2 + 1] = ((uint32_t)i1 << 20) | (uint32_t)p1;
        d_wtok[t * 2 + 0] = w0;
        d_wtok[t * 2 + 1] = w1;
    }
}

// ---------------- GEMM: fp16-acc m16n8k16, 128x128 CTA, 4 warps ----------
// fp16 group accumulators over K=64, promoted to fp32 masters.
// Register-lean: B frags streamed (4 live), imm-offset ldmatrix, padded hmid.
constexpr int BM = 128, BN = 128, BK = 32;
constexpr int NT = 128;                            // threads per CTA
constexpr int BKW = 20;                            // padded words/row
constexpr int ROWB = BKW * 4;                      // 80 B per row
constexpr int A_STAGE_B = BM * ROWB;               // 10240 B
constexpr int B_STAGE_B = BN * ROWB;               // 10240 B
constexpr int STAGE_B   = A_STAGE_B + B_STAGE_B;   // 20480 B
constexpr int NSTAGE    = 5;
constexpr int SMEM_DYN  = NSTAGE * STAGE_B;        // 102400 B (2 CTAs -> 200 KB/SM)

template <bool FIRST>
__global__ __launch_bounds__(NT, 2)
void moe_gemm_kernel(const float* __restrict__ bias) {
    const int e   = blockIdx.z;
    const int cnt = d_counts[e];
    const int m0  = blockIdx.y * BM;
    if (m0 >= cnt) return;
    const int n0   = blockIdx.x * BN;
    constexpr int KDIM = FIRST ? HH : II;
    constexpr int NDIM = FIRST ? II : HH;
    const int offs = expert_offset(e);
    constexpr int NC = KDIM / BK;

    extern __shared__ char dynsmem[];
    const uint32_t sbase = smem_u32(dynsmem);

    const int tid = threadIdx.x;
    const int ldrow = tid >> 2;          // 0..31
    const int ldc16 = (tid & 3) * 16;    // byte offset of 16B chunk in row

    // A source element-offsets into the fp16 array (uint32; max < 2^28)
    const __half* aBase = FIRST ? d_xh : d_hmid;
    uint32_t aOff[4];
    if (FIRST) {
#pragma unroll
        for (int j = 0; j < 4; j++) {
            int gm = m0 + ldrow + j * 32;
            if (gm >= cnt) gm = cnt - 1;
            aOff[j] = (uint32_t)d_tok[e * TT + gm] * HH + (tid & 3) * 8;
        }
    } else {
        // padded d_hmid: no clamp needed; rows >= cnt read garbage, discarded
        aOff[0] = (uint32_t)(offs + m0 + ldrow) * II + (tid & 3) * 8;
#pragma unroll
        for (int j = 1; j < 4; j++) aOff[j] = aOff[0] + j * (32 * II);
    }
    // B source: single base + compile-time row strides (32 rows apart)
    const __half* bBase = (FIRST ? d_w1h : d_w2h)
        + (size_t)e * ((size_t)II * HH) + (size_t)(n0 + ldrow) * KDIM + (tid & 3) * 8;

    // smem store bases (stage 0)
    const uint32_t aSt0 = sbase + ldrow * ROWB + ldc16;
    const uint32_t bSt0 = sbase + A_STAGE_B + ldrow * ROWB + ldc16;

    // prologue: stages 0..3
#pragma unroll
    for (int s = 0; s < NSTAGE - 1; s++) {
        const uint32_t so = (uint32_t)(s * STAGE_B);
#pragma unroll
        for (int j = 0; j < 4; j++)
            CP_ASYNC16(aSt0 + so + j * (32 * ROWB), aBase + aOff[j] + s * BK);
#pragma unroll
        for (int j = 0; j < 4; j++)
            CP_ASYNC16(bSt0 + so + j * (32 * ROWB),
                       bBase + (size_t)j * 32 * KDIM + s * BK);
        CP_COMMIT();
    }

    const int wid = tid >> 5, lane = tid & 31;
    const int wm = (wid >> 1) * 64;       // 2 m-warps
    const int wn = (wid & 1) * 64;        // 2 n-warps
    const int g = lane >> 2, tg = lane & 3;

    // ldmatrix per-lane base addresses (single reg each; mf/nf2 via imm offs)
    uint32_t aLd0, bLd0;
    {
        int row = wm + (lane & 7) + ((lane >> 3) & 1) * 8;
        int col = ((lane >> 4) & 1) * 16;
        aLd0 = sbase + row * ROWB + col;
        int rowb = wn + (lane & 7) + ((lane >> 4) & 1) * 8;
        int colb = ((lane >> 3) & 1) * 16;
        bLd0 = sbase + A_STAGE_B + rowb * ROWB + colb;
    }

    float acc[4][8][4];                 // fp32 masters
#pragma unroll
    for (int a = 0; a < 4; a++)
#pragma unroll
        for (int b = 0; b < 8; b++)
#pragma unroll
            for (int c = 0; c < 4; c++) acc[a][b][c] = 0.0f;

    uint32_t acch[4][8][2];             // fp16x2 group accumulators

    CP_WAIT3();
    __syncthreads();

    int stage = 0;
#pragma unroll 1
    for (int grp = 0; grp < NC / 2; grp++) {
#pragma unroll
        for (int halfc = 0; halfc < 2; halfc++) {
            const int i = grp * 2 + halfc;
            const uint32_t stoff = (uint32_t)(stage * STAGE_B);

#pragma unroll
            for (int kk = 0; kk < 2; kk++) {
                const uint32_t ko = stoff + kk * 32;
                uint32_t af[4][4];
                ldsm_off<0 * 16 * ROWB>(af[0][0], af[0][1], af[0][2], af[0][3], aLd0 + ko);
                ldsm_off<1 * 16 * ROWB>(af[1][0], af[1][1], af[1][2], af[1][3], aLd0 + ko);
                ldsm_off<2 * 16 * ROWB>(af[2][0], af[2][1], af[2][2], af[2][3], aLd0 + ko);
                ldsm_off<3 * 16 * ROWB>(af[3][0], af[3][1], af[3][2], af[3][3], aLd0 + ko);
#pragma unroll
                for (int nf2 = 0; nf2 < 4; nf2++) {
                    uint32_t b0, b1, b2, b3;
                    if (nf2 == 0) ldsm_off<0 * 16 * ROWB>(b0, b1, b2, b3, bLd0 + ko);
                    if (nf2 == 1) ldsm_off<1 * 16 * ROWB>(b0, b1, b2, b3, bLd0 + ko);
                    if (nf2 == 2) ldsm_off<2 * 16 * ROWB>(b0, b1, b2, b3, bLd0 + ko);
                    if (nf2 == 3) ldsm_off<3 * 16 * ROWB>(b0, b1, b2, b3, bLd0 + ko);
                    if (halfc == 0 && kk == 0) {
#pragma unroll
                        for (int mf = 0; mf < 4; mf++) {
                            MMA_F16Z(acch[mf][2 * nf2 + 0], af[mf], b0, b1);
                            MMA_F16Z(acch[mf][2 * nf2 + 1], af[mf], b2, b3);
                        }
                    } else {
#pragma unroll
                        for (int mf = 0; mf < 4; mf++) {
                            MMA_F16H(acch[mf][2 * nf2 + 0], af[mf], b0, b1);
                            MMA_F16H(acch[mf][2 * nf2 + 1], af[mf], b2, b3);
                        }
                    }
                }
            }

            // prefetch chunk i+4
            const int nx = i + NSTAGE - 1;
            if (nx < NC) {
                int s = stage - 1; if (s < 0) s = NSTAGE - 1;   // (i+4) mod 5
                const uint32_t so = (uint32_t)(s * STAGE_B);
#pragma unroll
                for (int j = 0; j < 4; j++)
                    CP_ASYNC16(aSt0 + so + j * (32 * ROWB), aBase + aOff[j] + nx * BK);
#pragma unroll
                for (int j = 0; j < 4; j++)
                    CP_ASYNC16(bSt0 + so + j * (32 * ROWB),
                               bBase + (size_t)j * 32 * KDIM + nx * BK);
            }
            CP_COMMIT();

            // promote at group end (hides in cp.async latency, before wait)
            if (halfc == 1) {
#pragma unroll
                for (int mf = 0; mf < 4; mf++)
#pragma unroll
                    for (int nf = 0; nf < 8; nf++) {
#pragma unroll
                        for (int d = 0; d < 2; d++) {
                            float2 f = __half22float2(*(__half2*)&acch[mf][nf][d]);
                            acc[mf][nf][2 * d + 0] += f.x;
                            acc[mf][nf][2 * d + 1] += f.y;
                        }
                    }
            }

            if (i + 1 < NC) {
                CP_WAIT3();
                __syncthreads();
            }
            stage = (stage + 1 == NSTAGE) ? 0 : stage + 1;
        }
    }

    // epilogue (acc: d0,d1 = row g cols 2tg,2tg+1; d2,d3 = row g+8)
#pragma unroll
    for (int mf = 0; mf < 4; mf++) {
#pragma unroll
        for (int half = 0; half < 2; half++) {
            int m = m0 + wm + mf * 16 + g + half * 8;
            if (m >= cnt) continue;
            if (FIRST) {
                __half* dst = d_hmid + (size_t)(offs + m) * II + n0;
#pragma unroll
                for (int nf = 0; nf < 8; nf++) {
                    int col = wn + nf * 8 + tg * 2;
                    float bb0 = bias[(size_t)e * NDIM + n0 + col];
                    float bb1 = bias[(size_t)e * NDIM + n0 + col + 1];
                    float s0 = silu_f(acc[mf][nf][half * 2 + 0] + bb0);
                    float s1 = silu_f(acc[mf][nf][half * 2 + 1] + bb1);
                    *(__half2*)(dst + col) = __floats2half2_rn(s0, s1);
                }
            } else {
                float* dst = d_osc + (size_t)(offs + m) * HH + n0;
#pragma unroll
                for (int nf = 0; nf < 8; nf++) {
                    int col = wn + nf * 8 + tg * 2;
                    float bb0 = bias[(size_t)e * NDIM + n0 + col];
                    float bb1 = bias[(size_t)e * NDIM + n0 + col + 1];
                    *(float2*)(dst + col) = make_float2(acc[mf][nf][half * 2 + 0] + bb0,
                                                        acc[mf][nf][half * 2 + 1] + bb1);
                }
            }
        }
    }
}

// ---------------- kernel: combine two expert rows per token ----------------
__global__ __launch_bounds__(256)
void combine_kernel(float* __restrict__ out) {
    const int t = blockIdx.x;
    const uint32_t s0 = d_slotEP[t * 2 + 0];
    const uint32_t s1 = d_slotEP[t * 2 + 1];
    const int e0 = (int)(s0 >> 20), p0 = (int)(s0 & 0xFFFFFu);
    const int e1 = (int)(s1 >> 20), p1 = (int)(s1 & 0xFFFFFu);
    const float w0 = d_wtok[t * 2 + 0];
    const float w1 = d_wtok[t * 2 + 1];
    const size_t r0 = (size_t)(expert_offset(e0) + p0) * HH;
    const size_t r1 = (size_t)(expert_offset(e1) + p1) * HH;
    const float4* a = (const float4*)(d_osc + r0);
    const float4* b = (const float4*)(d_osc + r1);
    float4* o = (float4*)(out + (size_t)t * HH);
    const int k = threadIdx.x;           // 256 threads x float4 = 1024
    float4 va = a[k], vb = b[k];
    float4 vo;
    vo.x = w0 * va.x + w1 * vb.x;
    vo.y = w0 * va.y + w1 * vb.y;
    vo.z = w0 * va.z + w1 * vb.z;
    vo.w = w0 * va.w + w1 * vb.w;
    o[k] = vo;
}

// ---------------- launch ----------------
extern "C" void kernel_launch(void* const* d_in, const int* in_sizes, int n_in,
                              void* d_out, int out_size) {
    const float* x  = (const float*)d_in[0];   // [T,H]
    const float* Wg = (const float*)d_in[1];   // [E,H]
    const float* W1 = (const float*)d_in[2];   // [E,I,H]
    const float* b1 = (const float*)d_in[3];   // [E,I]
    const float* W2 = (const float*)d_in[4];   // [E,H,I]
    const float* b2 = (const float*)d_in[5];   // [E,H]
    float* out = (float*)d_out;

    float* logits = nullptr;
    if ((size_t)out_size >= (size_t)TT * HH + (size_t)TT * EE)
        logits = out + (size_t)TT * HH;

    cudaFuncSetAttribute(moe_gemm_kernel<true>,  cudaFuncAttributeMaxDynamicSharedMemorySize, SMEM_DYN);
    cudaFuncSetAttribute(moe_gemm_kernel<false>, cudaFuncAttributeMaxDynamicSharedMemorySize, SMEM_DYN);

    cvt_f16_kernel<<<4096, 256>>>((const float4*)W1, 1, (size_t)EE * II * HH / 4);  // zeroes counts
    cvt_f16_kernel<<<4096, 256>>>((const float4*)W2, 2, (size_t)EE * HH * II / 4);
    router_kernel<<<TT / 8, 256>>>(x, Wg, logits);   // also writes d_xh + slots

    dim3 g1(II / BN, TT / BM, EE);   // (32, 128, 8) -- 4th launch: ncu profiles this
    moe_gemm_kernel<true><<<g1, NT, SMEM_DYN>>>(b1);

    dim3 g2(HH / BN, TT / BM, EE);   // (8, 128, 8)
    moe_gemm_kernel<false><<<g2, NT, SMEM_DYN>>>(b2);

    combine_kernel<<<TT, 256>>>(out);
}

// round 17
// speedup vs baseline: 2.1041x; 1.3155x over previous
#include <cuda_runtime.h>
#include <cuda_fp16.h>
#include <cstdint>

// Problem constants
#define TT 16384   // B*S tokens
#define HH 1024    // hidden
#define II 4096    // intermediate
#define EE 8       // experts

// ---------------- scratch (device globals; no runtime allocation) ----------
__device__ int      d_counts[EE];
__device__ int      d_tok[EE * TT];
__device__ uint32_t d_slotEP[2 * TT];             // (expert<<20)|pos per token slot
__device__ float    d_wtok[2 * TT];               // per-token top-2 weights
// +128 pad rows: unclamped tail reads of the last tile stay in-bounds
__device__ __half   d_hmid[(size_t)(2 * TT + 128) * II];
__device__ float    d_osc[(size_t)2 * TT * HH];   // fp32 expert outputs (134 MB)
__device__ __half   d_xh[(size_t)TT * HH];        // fp16 x (written by router)
__device__ __half   d_w1h[(size_t)EE * II * HH];  // fp16 W1
__device__ __half   d_w2h[(size_t)EE * HH * II];  // fp16 W2

// ---------------- helpers ----------------
__device__ __forceinline__ float silu_f(float v) { return v / (1.0f + __expf(-v)); }
__device__ __forceinline__ uint32_t smem_u32(const void* p) {
    uint32_t a;
    asm("{ .reg .u64 t; cvta.to.shared.u64 t, %1; cvt.u32.u64 %0, t; }" : "=r"(a) : "l"(p));
    return a;
}
__device__ __forceinline__ int expert_offset(int e) {
    int off = 0;
#pragma unroll
    for (int q = 0; q < EE; q++) off += (q < e) ? d_counts[q] : 0;
    return off;
}

// fp32-accumulate fp16 MMA (R12 configuration)
#define MMA_F16(D, A, B_)                                                        \
    asm volatile(                                                                \
        "mma.sync.aligned.m16n8k16.row.col.f32.f16.f16.f32 "                     \
        "{%0,%1,%2,%3}, {%4,%5,%6,%7}, {%8,%9}, {%0,%1,%2,%3};\n"                \
        : "+f"((D)[0]), "+f"((D)[1]), "+f"((D)[2]), "+f"((D)[3])                 \
        : "r"((A)[0]), "r"((A)[1]), "r"((A)[2]), "r"((A)[3]),                    \
          "r"((B_)[0]), "r"((B_)[1]))

#define LDSM_X4(r0, r1, r2, r3, addr)                                            \
    asm volatile("ldmatrix.sync.aligned.m8n8.x4.shared.b16 {%0,%1,%2,%3}, [%4];" \
        : "=r"(r0), "=r"(r1), "=r"(r2), "=r"(r3) : "r"(addr))

#define CP_ASYNC16(saddr, gptr) \
    asm volatile("cp.async.cg.shared.global [%0], [%1], 16;" :: "r"(saddr), "l"(gptr) : "memory")
#define CP_COMMIT() asm volatile("cp.async.commit_group;" ::: "memory")
#define CP_WAIT1()  asm volatile("cp.async.wait_group 1;" ::: "memory")

// ---------------- kernel: fp32 -> fp16 weight conversion (+zero counters) --
__global__ __launch_bounds__(256)
void cvt_f16_kernel(const float4* __restrict__ src, int which, size_t n4) {
    if (which == 1 && blockIdx.x == 0 && threadIdx.x < EE)
        d_counts[threadIdx.x] = 0;
    __half* dstb = (which == 1) ? d_w1h : d_w2h;
    uint2* dst = (uint2*)dstb;
    size_t i  = (size_t)blockIdx.x * blockDim.x + threadIdx.x;
    size_t st = (size_t)gridDim.x * blockDim.x;
    for (; i < n4; i += st) {
        float4 v = src[i];
        __half2 h0 = __floats2half2_rn(v.x, v.y);
        __half2 h1 = __floats2half2_rn(v.z, v.w);
        uint2 o;
        o.x = *(uint32_t*)&h0;
        o.y = *(uint32_t*)&h1;
        dst[i] = o;
    }
}

// ---------------- kernel: router (fp32) + fused x->fp16 + slot record ------
__global__ __launch_bounds__(256)
void router_kernel(const float* __restrict__ x,
                   const float* __restrict__ Wg,
                   float* __restrict__ logits_out) {
    __shared__ float sWg[EE][HH];
    for (int i = threadIdx.x; i < EE * HH; i += blockDim.x)
        sWg[i / HH][i % HH] = Wg[i];
    __syncthreads();

    const int warp = threadIdx.x >> 5;
    const int lane = threadIdx.x & 31;
    const int t = blockIdx.x * 8 + warp;
    if (t >= TT) return;

    const float* xr = x + (size_t)t * HH;

    // fused x -> fp16
    {
        uint2* xo = (uint2*)(d_xh + (size_t)t * HH);
        const float4* xi = (const float4*)xr;
        for (int k4 = lane; k4 < HH / 4; k4 += 32) {
            float4 v = xi[k4];
            __half2 h0 = __floats2half2_rn(v.x, v.y);
            __half2 h1 = __floats2half2_rn(v.z, v.w);
            uint2 o;
            o.x = *(uint32_t*)&h0;
            o.y = *(uint32_t*)&h1;
            xo[k4] = o;
        }
    }

    float acc[EE];
#pragma unroll
    for (int e = 0; e < EE; e++) acc[e] = 0.0f;
    for (int k = lane; k < HH; k += 32) {
        float xv = xr[k];
#pragma unroll
        for (int e = 0; e < EE; e++) acc[e] += xv * sWg[e][k];
    }
#pragma unroll
    for (int off = 16; off > 0; off >>= 1)
#pragma unroll
        for (int e = 0; e < EE; e++)
            acc[e] += __shfl_xor_sync(0xFFFFFFFFu, acc[e], off);

    if (lane == 0) {
        if (logits_out)
#pragma unroll
            for (int e = 0; e < EE; e++) logits_out[(size_t)t * EE + e] = acc[e];
        int i0 = 0; float v0 = acc[0];
#pragma unroll
        for (int e = 1; e < EE; e++) if (acc[e] > v0) { v0 = acc[e]; i0 = e; }
        int i1 = -1; float v1 = -3.4e38f;
#pragma unroll
        for (int e = 0; e < EE; e++)
            if (e != i0 && acc[e] > v1) { v1 = acc[e]; i1 = e; }
        float r  = expf(v1 - v0);
        float w0 = 1.0f / (1.0f + r);
        float w1 = 1.0f - w0;
        int p0 = atomicAdd(&d_counts[i0], 1);
        d_tok[i0 * TT + p0] = t;
        int p1 = atomicAdd(&d_counts[i1], 1);
        d_tok[i1 * TT + p1] = t;
        d_slotEP[t * 2 + 0] = ((uint32_t)i0 << 20) | (uint32_t)p0;
        d_slotEP[t * 2 + 1] = ((uint32_t)i1 << 20) | (uint32_t)p1;
        d_wtok[t * 2 + 0] = w0;
        d_wtok[t * 2 + 1] = w1;
    }
}

// ---------------- GEMM: fp32-acc fp16 m16n8k16, 128x128 CTA, 4 warps -----
// BK=64 (4 k16 steps/chunk), 3-stage cp.async, double-buffered frags,
// cp.async issues interleaved into kk0's MMA block. 2 CTAs/SM.
constexpr int BM = 128, BN = 128, BK = 64;
constexpr int NT = 128;                            // threads per CTA
constexpr int ROWB = 144;                          // 128 B data + 16 B pad
constexpr int A_STAGE_B = BM * ROWB;               // 18432 B
constexpr int B_STAGE_B = BN * ROWB;               // 18432 B
constexpr int STAGE_B   = A_STAGE_B + B_STAGE_B;   // 36864 B
constexpr int NSTAGE    = 3;
constexpr int SMEM_DYN  = NSTAGE * STAGE_B;        // 110592 B (2 CTAs -> 216 KB/SM)

__device__ __forceinline__ void load_frags(uint32_t af[4][4], uint32_t bf[8][2],
                                           const uint32_t aLd[4], const uint32_t bLd[4],
                                           uint32_t ko) {
#pragma unroll
    for (int mf = 0; mf < 4; mf++)
        LDSM_X4(af[mf][0], af[mf][1], af[mf][2], af[mf][3], aLd[mf] + ko);
#pragma unroll
    for (int j = 0; j < 4; j++)
        LDSM_X4(bf[2 * j][0], bf[2 * j][1], bf[2 * j + 1][0], bf[2 * j + 1][1],
                bLd[j] + ko);
}

__device__ __forceinline__ void mma_all(float acc[4][8][4],
                                        const uint32_t af[4][4],
                                        const uint32_t bf[8][2]) {
#pragma unroll
    for (int mf = 0; mf < 4; mf++)
#pragma unroll
        for (int nf = 0; nf < 8; nf++)
            MMA_F16(acc[mf][nf], af[mf], bf[nf]);
}

template <bool FIRST>
__global__ __launch_bounds__(NT, 2)
void moe_gemm_kernel(const float* __restrict__ bias) {
    const int e   = blockIdx.z;
    const int cnt = d_counts[e];
    const int m0  = blockIdx.y * BM;
    if (m0 >= cnt) return;
    const int n0   = blockIdx.x * BN;
    constexpr int KDIM = FIRST ? HH : II;
    constexpr int NDIM = FIRST ? II : HH;
    const int offs = expert_offset(e);
    constexpr int NC = KDIM / BK;

    extern __shared__ char dynsmem[];
    const uint32_t sbase = smem_u32(dynsmem);

    const int tid = threadIdx.x;
    const int ldrow = tid >> 3;          // 0..15 (base row; rows j*16 apart)
    const int ldc8  = (tid & 7) * 8;     // element offset of 16B chunk in row

    // A source element-offsets (uint32; max < 2^28)
    const __half* aBase = FIRST ? d_xh : d_hmid;
    uint32_t aOff[8];
    if (FIRST) {
#pragma unroll
        for (int j = 0; j < 8; j++) {
            int gm = m0 + ldrow + j * 16;
            if (gm >= cnt) gm = cnt - 1;
            aOff[j] = (uint32_t)d_tok[e * TT + gm] * HH + ldc8;
        }
    } else {
        // padded d_hmid: no clamp; rows >= cnt read garbage, discarded later
        aOff[0] = (uint32_t)(offs + m0 + ldrow) * II + ldc8;
#pragma unroll
        for (int j = 1; j < 8; j++) aOff[j] = aOff[0] + j * (16 * II);
    }
    // B source: single base + compile-time row strides (16 rows apart)
    const __half* bBase = (FIRST ? d_w1h : d_w2h)
        + (size_t)e * ((size_t)II * HH) + (size_t)(n0 + ldrow) * KDIM + ldc8;

    // smem store bases (stage 0)
    const uint32_t aSt0 = sbase + ldrow * ROWB + (tid & 7) * 16;
    const uint32_t bSt0 = sbase + A_STAGE_B + ldrow * ROWB + (tid & 7) * 16;

    // prologue: chunks 0,1 into stages 0,1
#pragma unroll
    for (int s = 0; s < NSTAGE - 1; s++) {
        const uint32_t so = (uint32_t)(s * STAGE_B);
#pragma unroll
        for (int j = 0; j < 8; j++)
            CP_ASYNC16(aSt0 + so + j * (16 * ROWB), aBase + aOff[j] + s * BK);
#pragma unroll
        for (int j = 0; j < 8; j++)
            CP_ASYNC16(bSt0 + so + j * (16 * ROWB),
                       bBase + (size_t)j * 16 * KDIM + s * BK);
        CP_COMMIT();
    }

    const int wid = tid >> 5, lane = tid & 31;
    const int wm = (wid >> 1) * 64;       // 2 m-warps
    const int wn = (wid & 1) * 64;        // 2 n-warps
    const int g = lane >> 2, tg = lane & 3;

    // ldmatrix per-lane base addresses
    uint32_t aLd[4];
#pragma unroll
    for (int mf = 0; mf < 4; mf++) {
        int row = wm + mf * 16 + (lane & 7) + ((lane >> 3) & 1) * 8;
        int col = ((lane >> 4) & 1) * 16;
        aLd[mf] = sbase + row * ROWB + col;
    }
    uint32_t bLd[4];
#pragma unroll
    for (int nf2 = 0; nf2 < 4; nf2++) {
        int row = wn + nf2 * 16 + (lane & 7) + ((lane >> 4) & 1) * 8;
        int col = ((lane >> 3) & 1) * 16;
        bLd[nf2] = sbase + A_STAGE_B + row * ROWB + col;
    }

    float acc[4][8][4];
#pragma unroll
    for (int a = 0; a < 4; a++)
#pragma unroll
        for (int b = 0; b < 8; b++)
#pragma unroll
            for (int c = 0; c < 4; c++) acc[a][b][c] = 0.0f;

    uint32_t afc[4][4], bfc[8][2], afn[4][4], bfn[8][2];

    CP_WAIT1();
    __syncthreads();
    load_frags(afc, bfc, aLd, bLd, 0u);        // chunk 0, kk0

    int stage = 0;
#pragma unroll 1
    for (int i = 0; i < NC; i++) {
        const uint32_t stoff = (uint32_t)(stage * STAGE_B);

        // kk0 MMAs with prefetch of chunk i+2 interleaved (16 cp.async)
        load_frags(afn, bfn, aLd, bLd, stoff + 32);      // kk1
        {
            const int  nx = i + NSTAGE - 1;
            const bool pf = nx < NC;
            int ps = stage + 2; if (ps >= NSTAGE) ps -= NSTAGE;   // (i+2) mod 3
            const uint32_t so = (uint32_t)(ps * STAGE_B);
#pragma unroll
            for (int mf = 0; mf < 4; mf++) {
#pragma unroll
                for (int nf = 0; nf < 8; nf++) {
                    MMA_F16(acc[mf][nf], afc[mf], bfc[nf]);
                    const int q = mf * 8 + nf;
                    if (pf && (q & 1) == 0) {
                        const int idx = q >> 1;
                        if (idx < 8)
                            CP_ASYNC16(aSt0 + so + idx * (16 * ROWB),
                                       aBase + aOff[idx] + nx * BK);
                        else
                            CP_ASYNC16(bSt0 + so + (idx - 8) * (16 * ROWB),
                                       bBase + (size_t)(idx - 8) * 16 * KDIM + nx * BK);
                    }
                }
            }
            CP_COMMIT();
        }

        load_frags(afc, bfc, aLd, bLd, stoff + 64);      // kk2
        mma_all(acc, afn, bfn);                          // kk1
        load_frags(afn, bfn, aLd, bLd, stoff + 96);      // kk3
        mma_all(acc, afc, bfc);                          // kk2

        int nstage = stage + 1; if (nstage == NSTAGE) nstage = 0;
        if (i + 1 < NC) {
            CP_WAIT1();
            __syncthreads();
            load_frags(afc, bfc, aLd, bLd, (uint32_t)(nstage * STAGE_B));  // next kk0
        }
        mma_all(acc, afn, bfn);                          // kk3
        stage = nstage;
    }

    // epilogue (acc: d0,d1 = row g cols 2tg,2tg+1; d2,d3 = row g+8)
#pragma unroll
    for (int mf = 0; mf < 4; mf++) {
#pragma unroll
        for (int half = 0; half < 2; half++) {
            int m = m0 + wm + mf * 16 + g + half * 8;
            if (m >= cnt) continue;
            if (FIRST) {
                __half* dst = d_hmid + (size_t)(offs + m) * II + n0;
#pragma unroll
                for (int nf = 0; nf < 8; nf++) {
                    int col = wn + nf * 8 + tg * 2;
                    float bb0 = bias[(size_t)e * NDIM + n0 + col];
                    float bb1 = bias[(size_t)e * NDIM + n0 + col + 1];
                    float s0 = silu_f(acc[mf][nf][half * 2 + 0] + bb0);
                    float s1 = silu_f(acc[mf][nf][half * 2 + 1] + bb1);
                    *(__half2*)(dst + col) = __floats2half2_rn(s0, s1);
                }
            } else {
                float* dst = d_osc + (size_t)(offs + m) * HH + n0;
#pragma unroll
                for (int nf = 0; nf < 8; nf++) {
                    int col = wn + nf * 8 + tg * 2;
                    float bb0 = bias[(size_t)e * NDIM + n0 + col];
                    float bb1 = bias[(size_t)e * NDIM + n0 + col + 1];
                    *(float2*)(dst + col) = make_float2(acc[mf][nf][half * 2 + 0] + bb0,
                                                        acc[mf][nf][half * 2 + 1] + bb1);
                }
            }
        }
    }
}

// ---------------- kernel: combine two expert rows per token ----------------
__global__ __launch_bounds__(256)
void combine_kernel(float* __restrict__ out) {
    const int t = blockIdx.x;
    const uint32_t s0 = d_slotEP[t * 2 + 0];
    const uint32_t s1 = d_slotEP[t * 2 + 1];
    const int e0 = (int)(s0 >> 20), p0 = (int)(s0 & 0xFFFFFu);
    const int e1 = (int)(s1 >> 20), p1 = (int)(s1 & 0xFFFFFu);
    const float w0 = d_wtok[t * 2 + 0];
    const float w1 = d_wtok[t * 2 + 1];
    const size_t r0 = (size_t)(expert_offset(e0) + p0) * HH;
    const size_t r1 = (size_t)(expert_offset(e1) + p1) * HH;
    const float4* a = (const float4*)(d_osc + r0);
    const float4* b = (const float4*)(d_osc + r1);
    float4* o = (float4*)(out + (size_t)t * HH);
    const int k = threadIdx.x;           // 256 threads x float4 = 1024
    float4 va = a[k], vb = b[k];
    float4 vo;
    vo.x = w0 * va.x + w1 * vb.x;
    vo.y = w0 * va.y + w1 * vb.y;
    vo.z = w0 * va.z + w1 * vb.z;
    vo.w = w0 * va.w + w1 * vb.w;
    o[k] = vo;
}

// ---------------- launch ----------------
extern "C" void kernel_launch(void* const* d_in, const int* in_sizes, int n_in,
                              void* d_out, int out_size) {
    const float* x  = (const float*)d_in[0];   // [T,H]
    const float* Wg = (const float*)d_in[1];   // [E,H]
    const float* W1 = (const float*)d_in[2];   // [E,I,H]
    const float* b1 = (const float*)d_in[3];   // [E,I]
    const float* W2 = (const float*)d_in[4];   // [E,H,I]
    const float* b2 = (const float*)d_in[5];   // [E,H]
    float* out = (float*)d_out;

    float* logits = nullptr;
    if ((size_t)out_size >= (size_t)TT * HH + (size_t)TT * EE)
        logits = out + (size_t)TT * HH;

    cudaFuncSetAttribute(moe_gemm_kernel<true>,  cudaFuncAttributeMaxDynamicSharedMemorySize, SMEM_DYN);
    cudaFuncSetAttribute(moe_gemm_kernel<false>, cudaFuncAttributeMaxDynamicSharedMemorySize, SMEM_DYN);

    cvt_f16_kernel<<<4096, 256>>>((const float4*)W1, 1, (size_t)EE * II * HH / 4);  // zeroes counts
    cvt_f16_kernel<<<4096, 256>>>((const float4*)W2, 2, (size_t)EE * HH * II / 4);
    router_kernel<<<TT / 8, 256>>>(x, Wg, logits);   // also writes d_xh + slots

    dim3 g1(II / BN, TT / BM, EE);   // (32, 128, 8) -- 4th launch: ncu profiles this
    moe_gemm_kernel<true><<<g1, NT, SMEM_DYN>>>(b1);

    dim3 g2(HH / BN, TT / BM, EE);   // (8, 128, 8)
    moe_gemm_kernel<false><<<g2, NT, SMEM_DYN>>>(b2);

    combine_kernel<<<TT, 256>>>(out);
}